// round 2
// baseline (speedup 1.0000x reference)
#include <cuda_runtime.h>

#define T_TOTAL 34
#define H_OFF   4
#define TN      30     // T_TOTAL - H_OFF
#define AP      128    // agents per ego group
#define NEGO    32

// 0 = uint8 mask, 1 = int32 mask, 2 = float32 mask
__device__ int g_vm_mode;

// Fused: detect valid-mask dtype + initialize out[] to 1.0
__global__ void ttc_init(const unsigned int* __restrict__ vm_words, float* out) {
    if (threadIdx.x < NEGO) out[threadIdx.x] = 1.0f;
    if (threadIdx.x == 0) {
        bool all01 = true, allf = true;
        #pragma unroll 8
        for (int i = 0; i < 64; i++) {
            unsigned int v = vm_words[i];
            all01 = all01 && (v == 0u || v == 1u);
            allf  = allf  && (v == 0u || v == 0x3F800000u);
        }
        g_vm_mode = all01 ? 1 : (allf ? 2 : 0);
    }
}

__device__ __forceinline__ bool vm_at(const void* vm, int idx, int mode) {
    if (mode == 1) return ((const int*)vm)[idx] != 0;
    if (mode == 2) return ((const float*)vm)[idx] != 0.0f;
    return ((const unsigned char*)vm)[idx] != 0;
}

// _loss over 4 corners (cx,cy) projected into frame at (px,py) with cos/sin (c,s),
// box extents (bf, br, bl, brt). Returns max over corners of min(long_t, lat_t).
__device__ __forceinline__ float corner_loss4(
    const float* cx, const float* cy, float px, float py,
    float c, float s, float bf, float br, float bl, float brt)
{
    float m = -1e30f;
    #pragma unroll
    for (int k = 0; k < 4; k++) {
        float dx = cx[k] - px, dy = cy[k] - py;
        float lx =  dx * c + dy * s;
        float ly = -dx * s + dy * c;
        float lt = fminf(fmaxf(bf  - lx, 0.0f), fmaxf(br  + lx, 0.0f));
        float la = fminf(fmaxf(bl  - ly, 0.0f), fmaxf(brt + ly, 0.0f));
        m = fmaxf(m, fminf(lt, la));
    }
    return m;
}

__global__ void __launch_bounds__(AP)
ttc_main(const float* __restrict__ posi,      // [N, 34, 2]
         const float* __restrict__ head,      // [N, 34]
         const float* __restrict__ box,       // [N, 4]  (f, r, l, rt)
         const void*  __restrict__ vm,        // [N, 34] bool (dtype detected)
         float* __restrict__ out)             // [32]
{
    const int mode = g_vm_mode;
    const int b  = blockIdx.x;     // ego group 0..31
    const int t  = blockIdx.y;     // 0..29
    const int ti = t + H_OFF;      // 4..33
    const int e  = b * AP;         // ego agent index (first of group)

    // Ego invalid at this t -> no valid edges for this (b,t): uniform early-out.
    if (!vm_at(vm, e * T_TOTAL + ti, mode)) return;

    __shared__ float s_ecx[4], s_ecy[4];
    __shared__ float s_epx, s_epy, s_ec, s_es;
    __shared__ float s_ebox[4];
    __shared__ int   s_any;

    const int tid = threadIdx.x;

    if (tid == 0) {
        s_any = 0;
        const int base = (e * T_TOTAL + ti) * 2;
        float ax = posi[base],     ay = posi[base + 1];
        float bx = posi[base - 2], by = posi[base - 1];
        float vx = (ax - bx) / 0.5f, vy = (ay - by) / 0.5f;   // vel = dp / DT
        float px = ax + vx * 0.95f,  py = ay + vy * 0.95f;    // pos + vel * TTC
        float yaw = head[e * T_TOTAL + ti];
        float c = cosf(yaw), s = sinf(yaw);
        float f  = box[e * 4 + 0], r  = box[e * 4 + 1];
        float l  = box[e * 4 + 2], rt = box[e * 4 + 3];
        const float lxs[4] = { f,  f, -r, -r };
        const float lys[4] = { l, -rt, -rt, l };
        #pragma unroll
        for (int k = 0; k < 4; k++) {
            s_ecx[k] = lxs[k] * c - lys[k] * s + px;
            s_ecy[k] = lxs[k] * s + lys[k] * c + py;
        }
        s_epx = px; s_epy = py; s_ec = c; s_es = s;
        s_ebox[0] = f; s_ebox[1] = r; s_ebox[2] = l; s_ebox[3] = rt;
    }
    __syncthreads();

    bool viol = false;
    if (tid != 0) {                     // tid 0 is the ego itself: excluded edge
        const int n = e + tid;
        if (vm_at(vm, n * T_TOTAL + ti, mode)) {
            const int base = (n * T_TOTAL + ti) * 2;
            float ax = posi[base],     ay = posi[base + 1];
            float bx = posi[base - 2], by = posi[base - 1];
            float vx = (ax - bx) / 0.5f, vy = (ay - by) / 0.5f;
            float px = ax + vx * 0.95f,  py = ay + vy * 0.95f;
            float yaw = head[n * T_TOTAL + ti];
            float ca = cosf(yaw), sa = sinf(yaw);
            float af  = box[n * 4 + 0], ar  = box[n * 4 + 1];
            float al  = box[n * 4 + 2], art = box[n * 4 + 3];

            // L1: ego corners in this agent's frame / box
            float L1 = corner_loss4(s_ecx, s_ecy, px, py, ca, sa, af, ar, al, art);

            // agent corners in world
            float acx[4], acy[4];
            const float lxs[4] = { af,  af, -ar, -ar };
            const float lys[4] = { al, -art, -art, al };
            #pragma unroll
            for (int k = 0; k < 4; k++) {
                acx[k] = lxs[k] * ca - lys[k] * sa + px;
                acy[k] = lxs[k] * sa + lys[k] * ca + py;
            }
            // L2: agent corners in ego frame / ego box
            float L2 = corner_loss4(acx, acy, s_epx, s_epy, s_ec, s_es,
                                    s_ebox[0], s_ebox[1], s_ebox[2], s_ebox[3]);

            viol = (fmaxf(L1, L2) > 0.0f);
        }
    }

    if (viol) s_any = 1;    // benign write race (same value)
    __syncthreads();
    if (tid == 0 && s_any) out[b] = 0.0f;  // benign cross-block same-value race
}

extern "C" void kernel_launch(void* const* d_in, const int* in_sizes, int n_in,
                              void* d_out, int out_size) {
    const float* posi = (const float*)d_in[0];         // infer_position
    const float* head = (const float*)d_in[1];         // infer_heading
    const float* box  = (const float*)d_in[2];         // box
    const void*  vm   = (const void*)d_in[3];          // infer_valid_mask (dtype unknown)
    // d_in[4] = batch, d_in[5] = ptr : structure is fixed by the problem constants.
    float* out = (float*)d_out;

    ttc_init<<<1, 32>>>((const unsigned int*)vm, out);
    dim3 grid(NEGO, TN);
    ttc_main<<<grid, AP>>>(posi, head, box, vm, out);
}

// round 3
// speedup vs baseline: 1.1254x; 1.1254x over previous
#include <cuda_runtime.h>

#define T_TOTAL 34
#define H_OFF   4
#define TN      30     // timesteps after H
#define AP      128    // agents per ego group
#define NEGO    32
#define NBLK    (NEGO * TN)

// Per-(b,t) violation flags + completion counter (self-resets each launch,
// so the kernel is graph-replay deterministic).
__device__ int          g_flags[NBLK];
__device__ unsigned int g_count;   // zero-initialized at load; returns to 0 every launch

__device__ __forceinline__ bool vm_at(const void* vm, int idx, int mode) {
    if (mode == 1) return ((const int*)vm)[idx] != 0;
    if (mode == 2) return ((const float*)vm)[idx] != 0.0f;
    return ((const unsigned char*)vm)[idx] != 0;
}

// max over 4 corners of min(long_t, lat_t) in a frame at (px,py) rot (c,s).
__device__ __forceinline__ float corner_loss4(
    const float* cx, const float* cy, float px, float py,
    float c, float s, float bf, float br, float bl, float brt)
{
    float m = -1e30f;
    #pragma unroll
    for (int k = 0; k < 4; k++) {
        float dx = cx[k] - px, dy = cy[k] - py;
        float lx =  dx * c + dy * s;
        float ly = -dx * s + dy * c;
        float lt = fminf(fmaxf(bf  - lx, 0.0f), fmaxf(br  + lx, 0.0f));
        float la = fminf(fmaxf(bl  - ly, 0.0f), fmaxf(brt + ly, 0.0f));
        m = fmaxf(m, fminf(lt, la));
    }
    return m;
}

__global__ void __launch_bounds__(AP)
ttc_fused(const float* __restrict__ posi,      // [N, 34, 2]
          const float* __restrict__ head,      // [N, 34]
          const float* __restrict__ box,       // [N, 4]  (f, r, l, rt)
          const void*  __restrict__ vm,        // [N, 34] bool (dtype detected)
          float* __restrict__ out)             // [32]
{
    const int b   = blockIdx.x;        // ego group
    const int t   = blockIdx.y;        // 0..29
    const int ti  = t + H_OFF;         // 4..33
    const int e   = b * AP;            // ego agent = first of group
    const int tid = threadIdx.x;

    // ---- valid-mask dtype detection: 8 broadcast word loads, uniform ----
    const unsigned int* w = (const unsigned int*)vm;
    bool all01 = true, allf = true;
    #pragma unroll
    for (int i = 0; i < 8; i++) {
        unsigned int v = w[i];
        all01 = all01 && (v <= 1u);
        allf  = allf  && (v == 0u || v == 0x3F800000u);
    }
    const int mode = all01 ? 1 : (allf ? 2 : 0);

    const int n  = e + tid;
    const bool ev = vm_at(vm, e * T_TOTAL + ti, mode);
    const bool av = (tid != 0) && vm_at(vm, n * T_TOTAL + ti, mode);

    bool viol = false;
    if (ev && av) {
        // All loads issue in one window (ego loads are warp-uniform broadcasts).
        const int ebp = (e * T_TOTAL + ti) * 2;
        const int abp = (n * T_TOTAL + ti) * 2;
        float2 ep0 = *(const float2*)(posi + ebp - 2);
        float2 ep1 = *(const float2*)(posi + ebp);
        float2 ap0 = *(const float2*)(posi + abp - 2);
        float2 ap1 = *(const float2*)(posi + abp);
        float  eyaw = head[e * T_TOTAL + ti];
        float  ayaw = head[n * T_TOTAL + ti];
        float4 eb = *(const float4*)(box + e * 4);   // f, r, l, rt
        float4 ab = *(const float4*)(box + n * 4);

        // pos + (dp / DT) * TTC ; (dp/0.5)*0.95 == dp*1.9 exactly in fp32
        float epx = fmaf(ep1.x - ep0.x, 1.9f, ep1.x);
        float epy = fmaf(ep1.y - ep0.y, 1.9f, ep1.y);
        float apx = fmaf(ap1.x - ap0.x, 1.9f, ap1.x);
        float apy = fmaf(ap1.y - ap0.y, 1.9f, ap1.y);

        float ce = cosf(eyaw), se = sinf(eyaw);
        float ca = cosf(ayaw), sa = sinf(ayaw);

        // ego corners (world)
        float ecx[4], ecy[4];
        {
            const float lxs[4] = { eb.x,  eb.x, -eb.y, -eb.y };
            const float lys[4] = { eb.z, -eb.w, -eb.w,  eb.z };
            #pragma unroll
            for (int k = 0; k < 4; k++) {
                ecx[k] = lxs[k] * ce - lys[k] * se + epx;
                ecy[k] = lxs[k] * se + lys[k] * ce + epy;
            }
        }
        // L1: ego corners in agent frame / agent box
        float L1 = corner_loss4(ecx, ecy, apx, apy, ca, sa, ab.x, ab.y, ab.z, ab.w);

        // agent corners (world)
        float acx[4], acy[4];
        {
            const float lxs[4] = { ab.x,  ab.x, -ab.y, -ab.y };
            const float lys[4] = { ab.z, -ab.w, -ab.w,  ab.z };
            #pragma unroll
            for (int k = 0; k < 4; k++) {
                acx[k] = lxs[k] * ca - lys[k] * sa + apx;
                acy[k] = lxs[k] * sa + lys[k] * ca + apy;
            }
        }
        // L2: agent corners in ego frame / ego box
        float L2 = corner_loss4(acx, acy, epx, epy, ce, se, eb.x, eb.y, eb.z, eb.w);

        viol = (fmaxf(L1, L2) > 0.0f);
    }

    // Block-wide OR (single BAR.RED), then last-block final reduction.
    int any = __syncthreads_or(viol ? 1 : 0);

    __shared__ bool s_last;
    if (tid == 0) {
        g_flags[b * TN + t] = any;
        __threadfence();
        unsigned int prev = atomicAdd(&g_count, 1u);
        bool last = (prev == NBLK - 1);
        s_last = last;
        if (last) g_count = 0;     // reset for next graph replay
    }
    __syncthreads();

    if (s_last) {
        __threadfence();           // acquire: flags from all blocks visible
        if (tid < NEGO) {
            int anyb = 0;
            #pragma unroll
            for (int k = 0; k < TN; k++) anyb |= g_flags[tid * TN + k];
            out[tid] = anyb ? 0.0f : 1.0f;
        }
    }
}

extern "C" void kernel_launch(void* const* d_in, const int* in_sizes, int n_in,
                              void* d_out, int out_size) {
    const float* posi = (const float*)d_in[0];   // infer_position
    const float* head = (const float*)d_in[1];   // infer_heading
    const float* box  = (const float*)d_in[2];   // box
    const void*  vm   = (const void*)d_in[3];    // infer_valid_mask
    float* out = (float*)d_out;

    dim3 grid(NEGO, TN);
    ttc_fused<<<grid, AP>>>(posi, head, box, vm, out);
}